// round 16
// baseline (speedup 1.0000x reference)
#include <cuda_runtime.h>
#include <math.h>

#define NC   2000   // codes
#define EV   32     // visits
#define DD   128    // embedding dim
#define HD   256    // hidden dim
#define NOUT 1000
#define NB   16     // batch
#define PAD  128    // max nnz per adj row/col
#define VCAP 128    // max codes per visit
#define PCH  16     // pool partial chunks
#define RPB  8      // rows per block in single-bit pass kernels
#define EPSF 1e-12f

// ---------------- scratch (device globals; no allocation) ----------------
static __device__ float d_icd[NC*DD];
static __device__ float d_buf[NC*DD];
static __device__ float d_EWh[NC*HD];
static __device__ float d_EWc[NC*HD];
static __device__ float d_IWi[NC*HD];

static __device__ int   d_rowcnt[NC];
static __device__ int   d_rowidx[NC*PAD];
static __device__ int   d_colcnt[NC];
static __device__ int   d_colidx[NC*PAD];

static __device__ unsigned d_vmask[NB*NC];
static __device__ unsigned d_smask[NB*NC];
static __device__ unsigned d_dmask[NB*NC];
static __device__ float d_Dvinv[NB*NC];
static __device__ int d_act[NB*NC];  static __device__ int d_actn[NB];
static __device__ int d_Sl[NB*NC];   static __device__ int d_Sn[NB];
static __device__ int d_Tl[NB*NC];   static __device__ int d_Tn[NB];
static __device__ int d_Sml[NB*NC];  static __device__ int d_Smn[NB];  // multi-bit S codes
static __device__ int d_Tml[NB*NC];  static __device__ int d_Tmn[NB];  // multi-bit T codes
static __device__ int d_spos[NB*NC];          // code -> S position
static __device__ int d_tpos[NB*NC];          // code -> T position
static __device__ int d_vl[NB*EV*VCAP];
static __device__ int d_vlen[NB*EV];
static __device__ unsigned d_Tdm[NB*NC];      // position-indexed T: dmask
static __device__ float    d_Tcv[NB*NC];      // position-indexed T: cinv
static __device__ unsigned d_Ssm[NB*NC];      // position-indexed S: smask
static __device__ float    d_Srv[NB*NC];      // position-indexed S: rinv
static __device__ float d_cinvc[NB*NC];       // code-indexed cinv (T codes)
static __device__ float d_rinvc[NB*NC];       // code-indexed rinv (S codes)
static __device__ float d_V1[(size_t)NB*EV*HD];
static __device__ float d_W2[(size_t)NB*EV*HD];
static __device__ float d_tph[NB*EV*HD];
static __device__ float d_tpi[NB*EV*HD];
static __device__ float d_yw[(size_t)NB*NC*HD];
static __device__ float d_zr[(size_t)NB*NC*HD];
static __device__ float d_pp[NB*PCH*3*HD];
static __device__ float d_eh[NB*HD], d_ec[NB*HD], d_ei[NB*HD];

__device__ __forceinline__ float warp_sum(float v){
  #pragma unroll
  for (int o=16;o>0;o>>=1) v += __shfl_down_sync(0xffffffffu, v, o);
  return v;
}
__device__ __forceinline__ float warp_allsum(float v){
  #pragma unroll
  for (int o=16;o>0;o>>=1) v += __shfl_xor_sync(0xffffffffu, v, o);
  return v;
}
__device__ __forceinline__ void fma4(float4& a, float s, const float4& e){
  a.x += s*e.x; a.y += s*e.y; a.z += s*e.z; a.w += s*e.w;
}

// ---------------- zero colcnt ----------------------------------------------------
__global__ void k_zero(){
  int t = blockIdx.x*blockDim.x + threadIdx.x;
  if (t < NC) d_colcnt[t] = 0;
}

// ---------------- CSR of adj + CSC scatter (warp per row) -------------------------
__global__ void k_csr_scat(const float* __restrict__ adj){
  int w = threadIdx.x >> 5, lane = threadIdx.x & 31;
  int r = blockIdx.x*32 + w;
  if (r >= NC) return;
  int cnt = 0;
  for (int jt=0; jt<NC; jt+=256){
    float v[8];
    #pragma unroll
    for (int u=0; u<8; u++){
      int j = jt + u*32 + lane;
      v[u] = (j < NC) ? adj[(size_t)r*NC + j] : 0.f;
    }
    #pragma unroll
    for (int u=0; u<8; u++){
      unsigned m = __ballot_sync(0xffffffffu, v[u] != 0.f);
      if (v[u] != 0.f){
        int pos = cnt + __popc(m & ((1u<<lane)-1u));
        if (pos < PAD) d_rowidx[r*PAD+pos] = jt + u*32 + lane;
      }
      cnt += __popc(m);
    }
  }
  if (cnt > PAD) cnt = PAD;
  if (lane == 0) d_rowcnt[r] = cnt;
  for (int p=lane; p<cnt; p+=32){
    int j = d_rowidx[r*PAD+p];
    int pos = atomicAdd(&d_colcnt[j], 1);
    if (pos < PAD) d_colidx[j*PAD+pos] = r;
  }
}

// ---------------- sparse y = adj @ x (warp per row, float4, unrolled) -------------
__global__ void k_spmm_rows(const float* __restrict__ emb, int use_icd){
  const float* src = use_icd ? d_icd : emb;
  int i = blockIdx.x*4 + (threadIdx.x>>5);
  int c = threadIdx.x & 31;
  int cnt = d_rowcnt[i];
  const int* idx = d_rowidx + i*PAD;
  float4 acc = make_float4(0.f,0.f,0.f,0.f);
  int p = 0;
  for (; p+4<=cnt; p+=4){
    int j0=idx[p], j1=idx[p+1], j2=idx[p+2], j3=idx[p+3];
    float4 v0 = *(const float4*)&src[(size_t)j0*DD + c*4];
    float4 v1 = *(const float4*)&src[(size_t)j1*DD + c*4];
    float4 v2 = *(const float4*)&src[(size_t)j2*DD + c*4];
    float4 v3 = *(const float4*)&src[(size_t)j3*DD + c*4];
    fma4(acc,1.f,v0); fma4(acc,1.f,v1); fma4(acc,1.f,v2); fma4(acc,1.f,v3);
  }
  for (; p<cnt; p++){
    float4 v = *(const float4*)&src[(size_t)idx[p]*DD + c*4];
    fma4(acc,1.f,v);
  }
  *(float4*)&d_buf[i*DD + c*4] = acc;
}

// ---------------- x = LN(adj.T @ buf) ----------------------------------------------
__global__ void k_spmm_cols_ln(const float* __restrict__ g, const float* __restrict__ b){
  int j = blockIdx.x*4 + (threadIdx.x>>5);
  int c = threadIdx.x & 31;
  int cnt = d_colcnt[j]; if (cnt > PAD) cnt = PAD;
  const int* idx = d_colidx + j*PAD;
  float4 acc = make_float4(0.f,0.f,0.f,0.f);
  int p = 0;
  for (; p+4<=cnt; p+=4){
    int j0=idx[p], j1=idx[p+1], j2=idx[p+2], j3=idx[p+3];
    float4 v0 = *(const float4*)&d_buf[(size_t)j0*DD + c*4];
    float4 v1 = *(const float4*)&d_buf[(size_t)j1*DD + c*4];
    float4 v2 = *(const float4*)&d_buf[(size_t)j2*DD + c*4];
    float4 v3 = *(const float4*)&d_buf[(size_t)j3*DD + c*4];
    fma4(acc,1.f,v0); fma4(acc,1.f,v1); fma4(acc,1.f,v2); fma4(acc,1.f,v3);
  }
  for (; p<cnt; p++){
    float4 v = *(const float4*)&d_buf[(size_t)idx[p]*DD + c*4];
    fma4(acc,1.f,v);
  }
  float m = warp_allsum(acc.x+acc.y+acc.z+acc.w) / (float)DD;
  float4 df = make_float4(acc.x-m, acc.y-m, acc.z-m, acc.w-m);
  float var = warp_allsum(df.x*df.x + df.y*df.y + df.z*df.z + df.w*df.w) / (float)DD;
  float r = rsqrtf(var + 1e-5f);
  float4 gg = *(const float4*)&g[c*4];
  float4 bb = *(const float4*)&b[c*4];
  float4 o;
  o.x = df.x*r*gg.x + bb.x; o.y = df.y*r*gg.y + bb.y;
  o.z = df.z*r*gg.z + bb.z; o.w = df.w*r*gg.w + bb.w;
  *(float4*)&d_icd[j*DD + c*4] = o;
}

// ---------------- dual GEMM: EWh = X@Wh, EWc = X@Wc (register-tiled) --------------
__global__ void k_gemm2(const float* __restrict__ X, const float* __restrict__ Wh,
                        const float* __restrict__ Wc){
  __shared__ float xs[16][DD];
  int r0 = blockIdx.x*16;
  int tid = threadIdx.x;
  for (int t=tid; t<16*DD; t+=256)
    xs[t>>7][t&127] = X[(size_t)(r0 + (t>>7))*DD + (t&127)];
  __syncthreads();
  int rg = tid>>6;
  int c4 = (tid&63)<<2;
  float4 ah0=make_float4(0,0,0,0), ah1=ah0, ah2=ah0, ah3=ah0;
  float4 ac0=ah0, ac1=ah0, ac2=ah0, ac3=ah0;
  const float* xrow = &xs[rg*4][0];
  for (int k=0; k<DD; k++){
    float4 wh = *(const float4*)&Wh[(size_t)k*HD + c4];
    float4 wc = *(const float4*)&Wc[(size_t)k*HD + c4];
    float x0 = xrow[k], x1 = xrow[DD+k], x2 = xrow[2*DD+k], x3 = xrow[3*DD+k];
    fma4(ah0,x0,wh); fma4(ah1,x1,wh); fma4(ah2,x2,wh); fma4(ah3,x3,wh);
    fma4(ac0,x0,wc); fma4(ac1,x1,wc); fma4(ac2,x2,wc); fma4(ac3,x3,wc);
  }
  int rbase = r0 + rg*4;
  *(float4*)&d_EWh[(size_t)(rbase+0)*HD + c4] = ah0;
  *(float4*)&d_EWh[(size_t)(rbase+1)*HD + c4] = ah1;
  *(float4*)&d_EWh[(size_t)(rbase+2)*HD + c4] = ah2;
  *(float4*)&d_EWh[(size_t)(rbase+3)*HD + c4] = ah3;
  *(float4*)&d_EWc[(size_t)(rbase+0)*HD + c4] = ac0;
  *(float4*)&d_EWc[(size_t)(rbase+1)*HD + c4] = ac1;
  *(float4*)&d_EWc[(size_t)(rbase+2)*HD + c4] = ac2;
  *(float4*)&d_EWc[(size_t)(rbase+3)*HD + c4] = ac3;
}

// ---------------- single GEMM: IWi = icd @ Wi -------------------------------------
__global__ void k_gemm1(const float* __restrict__ Wi){
  __shared__ float xs[16][DD];
  int r0 = blockIdx.x*16;
  int tid = threadIdx.x;
  for (int t=tid; t<16*DD; t+=256)
    xs[t>>7][t&127] = d_icd[(size_t)(r0 + (t>>7))*DD + (t&127)];
  __syncthreads();
  int rg = tid>>6;
  int c4 = (tid&63)<<2;
  float4 a0=make_float4(0,0,0,0), a1=a0, a2=a0, a3=a0;
  const float* xrow = &xs[rg*4][0];
  for (int k=0; k<DD; k++){
    float4 w = *(const float4*)&Wi[(size_t)k*HD + c4];
    float x0 = xrow[k], x1 = xrow[DD+k], x2 = xrow[2*DD+k], x3 = xrow[3*DD+k];
    fma4(a0,x0,w); fma4(a1,x1,w); fma4(a2,x2,w); fma4(a3,x3,w);
  }
  int rbase = r0 + rg*4;
  *(float4*)&d_IWi[(size_t)(rbase+0)*HD + c4] = a0;
  *(float4*)&d_IWi[(size_t)(rbase+1)*HD + c4] = a1;
  *(float4*)&d_IWi[(size_t)(rbase+2)*HD + c4] = a2;
  *(float4*)&d_IWi[(size_t)(rbase+3)*HD + c4] = a3;
}

// ---------------- fused masks + compactions (block per patient) --------------------
__global__ void k_masks_compact(const float* __restrict__ cx, const int* __restrict__ lens){
  __shared__ unsigned svm[NC];
  int b = blockIdx.x;
  int tid = threadIdx.x;
  int len = lens[b];
  unsigned lowm = (1u << (len-1)) - 1u;
  const float* cxb = cx + (size_t)b*EV*NC;
  for (int i=tid; i<NC; i+=1024){
    unsigned m = 0; int c = 0;
    for (int e=0; e<len; e++){
      if (cxb[(size_t)e*NC + i] != 0.f){ m |= (1u<<e); c++; }
    }
    svm[i] = m;
    d_vmask[b*NC+i] = m;
    d_Dvinv[b*NC+i] = rsqrtf(fmaxf((float)c, EPSF));
    d_smask[b*NC+i] = m & lowm;
    d_dmask[b*NC+i] = (m >> 1) & lowm;
  }
  __syncthreads();
  int w = tid>>5, lane = tid&31;
  unsigned ltm = (1u<<lane)-1u;
  {
    int cnt = 0;
    for (int base=0; base<NC; base+=32){
      int i = base + lane;
      bool v = (i<NC) && ((svm[i] >> w) & 1u);
      unsigned mm = __ballot_sync(0xffffffffu, v);
      if (v){
        int pos = cnt + __popc(mm & ltm);
        if (pos < VCAP) d_vl[((size_t)b*EV + w)*VCAP + pos] = i;
      }
      cnt += __popc(mm);
    }
    if (lane == 0) d_vlen[b*EV + w] = (cnt < VCAP) ? cnt : VCAP;
  }
  if (w < 5){
    int cnt = 0;
    for (int base=0; base<NC; base+=32){
      int i = base + lane;
      bool v = false;
      if (i < NC){
        unsigned m = svm[i];
        unsigned sm = m & lowm;
        unsigned dm = (m>>1) & lowm;
        if      (w==0) v = (m != 0u);
        else if (w==1) v = (sm != 0u);
        else if (w==2) v = (dm != 0u);
        else if (w==3) v = (__popc(sm) >= 2);
        else           v = (__popc(dm) >= 2);
      }
      unsigned mm = __ballot_sync(0xffffffffu, v);
      if (v){
        int pos = cnt + __popc(mm & ltm);
        if      (w==0) d_act[b*NC+pos] = i;
        else if (w==1){ d_Sl[b*NC+pos] = i; d_spos[b*NC+i] = pos; }
        else if (w==2){ d_Tl[b*NC+pos] = i; d_tpos[b*NC+i] = pos; }
        else if (w==3) d_Sml[b*NC+pos] = i;
        else           d_Tml[b*NC+pos] = i;
      }
      cnt += __popc(mm);
    }
    if (lane == 0){
      if      (w==0) d_actn[b] = cnt;
      else if (w==1) d_Sn[b]   = cnt;
      else if (w==2) d_Tn[b]   = cnt;
      else if (w==3) d_Smn[b]  = cnt;
      else           d_Tmn[b]  = cnt;
    }
  }
}

// -------- t'[e] (float4, block 64, MLP-unrolled) ---------------------------------------
__global__ void k_tprime(){
  int b = blockIdx.x, e = blockIdx.y, c = threadIdx.x;
  int n = d_vlen[b*EV + e];
  const int* vl = d_vl + ((size_t)b*EV + e)*VCAP;
  float4 ah = make_float4(0.f,0.f,0.f,0.f), ai = ah;
  int k = 0;
  for (; k+2<=n; k+=2){
    int i0 = vl[k], i1 = vl[k+1];
    float w0 = d_Dvinv[b*NC+i0], w1 = d_Dvinv[b*NC+i1];
    float4 h0 = *(const float4*)&d_EWh[(size_t)i0*HD + c*4];
    float4 v0 = *(const float4*)&d_IWi[(size_t)i0*HD + c*4];
    float4 h1 = *(const float4*)&d_EWh[(size_t)i1*HD + c*4];
    float4 v1 = *(const float4*)&d_IWi[(size_t)i1*HD + c*4];
    fma4(ah,w0,h0); fma4(ai,w0,v0);
    fma4(ah,w1,h1); fma4(ai,w1,v1);
  }
  for (; k<n; k++){
    int i = vl[k];
    float w = d_Dvinv[b*NC+i];
    float4 h = *(const float4*)&d_EWh[(size_t)i*HD + c*4];
    float4 v = *(const float4*)&d_IWi[(size_t)i*HD + c*4];
    fma4(ah,w,h); fma4(ai,w,v);
  }
  float inv = 1.f / fmaxf((float)n, EPSF);
  ah.x*=inv; ah.y*=inv; ah.z*=inv; ah.w*=inv;
  ai.x*=inv; ai.y*=inv; ai.z*=inv; ai.w*=inv;
  *(float4*)&d_tph[((size_t)b*EV+e)*HD + c*4] = ah;
  *(float4*)&d_tpi[((size_t)b*EV+e)*HD + c*4] = ai;
}

// -------- degrees of A + metadata (position- and code-indexed) -----------------------
__global__ void k_degrees(){
  __shared__ int      sIdx[NC];
  __shared__ unsigned sMsk[NC];
  int b = blockIdx.x, z = blockIdx.z;
  int Rn = z ? d_Tn[b] : d_Sn[b];
  int Cn = z ? d_Sn[b] : d_Tn[b];
  const int* rl = z ? (d_Tl + b*NC) : (d_Sl + b*NC);
  const int* cl = z ? (d_Sl + b*NC) : (d_Tl + b*NC);
  for (int q=threadIdx.x; q<Cn; q+=blockDim.x){
    int j = cl[q];
    sIdx[q] = j;
    sMsk[q] = z ? d_smask[b*NC+j] : d_dmask[b*NC+j];
  }
  __syncthreads();
  for (int p = blockIdx.y*blockDim.x + threadIdx.x; p < Rn; p += gridDim.y*blockDim.x){
    int i = rl[p];
    unsigned m = z ? d_dmask[b*NC+i] : d_smask[b*NC+i];
    float s = 0.f;
    for (int q=0; q<Cn; q++)
      s += ((m & sMsk[q]) && (sIdx[q] != i)) ? 1.f : 0.f;
    float inv = rsqrtf(fmaxf(s, EPSF));
    if (z){ d_Tdm[b*NC+p] = m; d_Tcv[b*NC+p] = inv; d_cinvc[b*NC+i] = inv; }
    else  { d_Ssm[b*NC+p] = m; d_Srv[b*NC+p] = inv; d_rinvc[b*NC+i] = inv; }
  }
}

// -------- V1[t] = sum_{j in visit t+1} cinv_j * EWc[j]  (256 thr, k-slice x4) ---------
__global__ void kV1(const int* __restrict__ lens){
  __shared__ float red[4][HD];
  int b = blockIdx.x, t = blockIdx.y;
  if (t >= lens[b]-1) return;
  int e = t+1;
  int n = d_vlen[b*EV + e];
  const int* vl = d_vl + ((size_t)b*EV + e)*VCAP;
  int s = threadIdx.x>>6, c = threadIdx.x&63;
  float4 acc = make_float4(0.f,0.f,0.f,0.f);
  for (int k=s; k<n; k+=4){
    int j = vl[k];
    float v = d_cinvc[b*NC+j];
    float4 ew = *(const float4*)&d_EWc[(size_t)j*HD + c*4];
    fma4(acc,v,ew);
  }
  *(float4*)&red[s][c*4] = acc;
  __syncthreads();
  if (s == 0){
    float4 a = acc;
    fma4(a,1.f,*(const float4*)&red[1][c*4]);
    fma4(a,1.f,*(const float4*)&red[2][c*4]);
    fma4(a,1.f,*(const float4*)&red[3][c*4]);
    *(float4*)&d_V1[((size_t)b*EV+t)*HD + c*4] = a;
  }
}

// -------- pass1 single-bit rows: yw[p] = rinv*(V1[t] - self) ---------------------------
__global__ void kF1s(){
  int b = blockIdx.x;
  int Sn = d_Sn[b];
  int p0 = blockIdx.y*RPB;
  if (p0 >= Sn) return;
  int g = threadIdx.x>>6, c = threadIdx.x&63;
  #pragma unroll
  for (int pick=0; pick<2; pick++){
    int p = p0 + g + pick*4;
    if (p >= Sn) break;
    unsigned sm = d_Ssm[b*NC+p];
    if (__popc(sm) != 1) continue;
    int code = d_Sl[b*NC+p];
    int t = __ffs(sm) - 1;
    float4 a = *(const float4*)&d_V1[((size_t)b*EV+t)*HD + c*4];
    if (d_dmask[b*NC+code] & sm){
      float cv = d_cinvc[b*NC+code];
      float4 e = *(const float4*)&d_EWc[(size_t)code*HD + c*4];
      a.x -= cv*e.x; a.y -= cv*e.y; a.z -= cv*e.z; a.w -= cv*e.w;
    }
    float rv = d_Srv[b*NC+p];
    a.x*=rv; a.y*=rv; a.z*=rv; a.w*=rv;
    *(float4*)&d_yw[((size_t)b*NC + p)*HD + c*4] = a;
  }
}

// -------- pass1 multi-bit rows: visit-list driven, lowest-bit dedup --------------------
// yw_i = rinv_i * sum over t in smask_i, j in vl[t+1], j!=i,
//        counted only where t == lowest bit of (smask_i & dmask_j)
__global__ void kF1m(){
  int b = blockIdx.x;
  int Smn = d_Smn[b];
  int g = threadIdx.x>>6, c = threadIdx.x&63;
  for (int r = blockIdx.y*4 + g; r < Smn; r += gridDim.y*4){
    int code = d_Sml[b*NC+r];
    unsigned sm = d_smask[b*NC+code];
    float4 acc = make_float4(0.f,0.f,0.f,0.f);
    unsigned mrem = sm;
    while (mrem){
      int t = __ffs(mrem) - 1; mrem &= mrem - 1u;
      unsigned below = (1u<<t) - 1u;
      int n = d_vlen[b*EV + t+1];
      const int* vl = d_vl + ((size_t)b*EV + t+1)*VCAP;
      for (int k=0; k<n; k++){
        int j = vl[k];
        unsigned x = sm & d_dmask[b*NC+j];   // bit t always set (j in visit t+1)
        if ((x & below) == 0u && j != code){
          float v = d_cinvc[b*NC+j];
          float4 e = *(const float4*)&d_EWc[(size_t)j*HD + c*4];
          fma4(acc,v,e);
        }
      }
    }
    float rv = d_rinvc[b*NC+code];
    acc.x*=rv; acc.y*=rv; acc.z*=rv; acc.w*=rv;
    int p = d_spos[b*NC+code];
    *(float4*)&d_yw[((size_t)b*NC + p)*HD + c*4] = acc;
  }
}

// -------- W2[t] = sum_{i in visit t} rinv_i * yw[spos_i]  (256 thr, k-slice x4) -------
__global__ void kW2(const int* __restrict__ lens){
  __shared__ float red[4][HD];
  int b = blockIdx.x, t = blockIdx.y;
  if (t >= lens[b]-1) return;
  int n = d_vlen[b*EV + t];
  const int* vl = d_vl + ((size_t)b*EV + t)*VCAP;
  int s = threadIdx.x>>6, c = threadIdx.x&63;
  float4 acc = make_float4(0.f,0.f,0.f,0.f);
  for (int k=s; k<n; k+=4){
    int i = vl[k];
    float v = d_rinvc[b*NC+i];
    int sp = d_spos[b*NC+i];
    float4 e = *(const float4*)&d_yw[((size_t)b*NC + sp)*HD + c*4];
    fma4(acc,v,e);
  }
  *(float4*)&red[s][c*4] = acc;
  __syncthreads();
  if (s == 0){
    float4 a = acc;
    fma4(a,1.f,*(const float4*)&red[1][c*4]);
    fma4(a,1.f,*(const float4*)&red[2][c*4]);
    fma4(a,1.f,*(const float4*)&red[3][c*4]);
    *(float4*)&d_W2[((size_t)b*EV+t)*HD + c*4] = a;
  }
}

// -------- pass2 single-bit rows: zr[q] = relu(cinv*(W2[t] - self) + b_c) ---------------
__global__ void kF2s(const float* __restrict__ b_c){
  int b = blockIdx.x;
  int Tn = d_Tn[b];
  int q0 = blockIdx.y*RPB;
  if (q0 >= Tn) return;
  int g = threadIdx.x>>6, c = threadIdx.x&63;
  float4 bc = *(const float4*)&b_c[c*4];
  #pragma unroll
  for (int pick=0; pick<2; pick++){
    int q = q0 + g + pick*4;
    if (q >= Tn) break;
    unsigned dm = d_Tdm[b*NC+q];
    if (__popc(dm) != 1) continue;
    int code = d_Tl[b*NC+q];
    int t = __ffs(dm) - 1;
    float4 a = *(const float4*)&d_W2[((size_t)b*EV+t)*HD + c*4];
    unsigned sj = d_smask[b*NC+code];
    if (sj & dm){
      float rvj = d_rinvc[b*NC+code];
      int sp = d_spos[b*NC+code];
      float4 e = *(const float4*)&d_yw[((size_t)b*NC + sp)*HD + c*4];
      a.x -= rvj*e.x; a.y -= rvj*e.y; a.z -= rvj*e.z; a.w -= rvj*e.w;
    }
    float cv = d_Tcv[b*NC+q];
    float4 o;
    o.x = fmaxf(cv*a.x + bc.x, 0.f); o.y = fmaxf(cv*a.y + bc.y, 0.f);
    o.z = fmaxf(cv*a.z + bc.z, 0.f); o.w = fmaxf(cv*a.w + bc.w, 0.f);
    *(float4*)&d_zr[((size_t)b*NC + q)*HD + c*4] = o;
  }
}

// -------- pass2 multi-bit rows: visit-list driven, lowest-bit dedup --------------------
// acc_j = sum over t in dmask_j, i in vl[t], i!=j,
//         counted only where t == lowest bit of (dmask_j & smask_i)
__global__ void kF2m(const float* __restrict__ b_c){
  int b = blockIdx.x;
  int Tmn = d_Tmn[b];
  int g = threadIdx.x>>6, c = threadIdx.x&63;
  float4 bc = *(const float4*)&b_c[c*4];
  for (int r = blockIdx.y*4 + g; r < Tmn; r += gridDim.y*4){
    int code = d_Tml[b*NC+r];
    unsigned dm = d_dmask[b*NC+code];
    float4 acc = make_float4(0.f,0.f,0.f,0.f);
    unsigned mrem = dm;
    while (mrem){
      int t = __ffs(mrem) - 1; mrem &= mrem - 1u;
      unsigned below = (1u<<t) - 1u;
      int n = d_vlen[b*EV + t];
      const int* vl = d_vl + ((size_t)b*EV + t)*VCAP;
      for (int k=0; k<n; k++){
        int i = vl[k];
        unsigned x = dm & d_smask[b*NC+i];   // bit t always set (i in visit t)
        if ((x & below) == 0u && i != code){
          float v = d_rinvc[b*NC+i];
          int sp = d_spos[b*NC+i];
          float4 e = *(const float4*)&d_yw[((size_t)b*NC + sp)*HD + c*4];
          fma4(acc,v,e);
        }
      }
    }
    float cv = d_cinvc[b*NC+code];
    float4 o;
    o.x = fmaxf(cv*acc.x + bc.x, 0.f); o.y = fmaxf(cv*acc.y + bc.y, 0.f);
    o.z = fmaxf(cv*acc.z + bc.z, 0.f); o.w = fmaxf(cv*acc.w + bc.w, 0.f);
    int q = d_tpos[b*NC+code];
    *(float4*)&d_zr[((size_t)b*NC + q)*HD + c*4] = o;
  }
}

// -------- pooled partials over PCH deterministic chunks (float4, block 64) ----------
__global__ void k_poolpart(const float* __restrict__ b_h, const float* __restrict__ b_i){
  int b = blockIdx.x, ch = blockIdx.y, c = threadIdx.x;
  int actn = d_actn[b], Tn = d_Tn[b];
  float4 bh = *(const float4*)&b_h[c*4];
  float4 bi = *(const float4*)&b_i[c*4];
  float4 ah = make_float4(0.f,0.f,0.f,0.f), ai = ah, ac = ah;
  for (int p=ch; p<actn; p+=PCH){
    int i = d_act[b*NC+p];
    unsigned m = d_vmask[b*NC+i];
    float w = d_Dvinv[b*NC+i];
    float4 sh = make_float4(0.f,0.f,0.f,0.f), si = sh;
    while (m){
      int e = __ffs(m) - 1; m &= (m-1u);
      float4 th = *(const float4*)&d_tph[((size_t)b*EV+e)*HD + c*4];
      float4 ti = *(const float4*)&d_tpi[((size_t)b*EV+e)*HD + c*4];
      fma4(sh,1.f,th); fma4(si,1.f,ti);
    }
    ah.x += fmaxf(w*sh.x + bh.x, 0.f); ah.y += fmaxf(w*sh.y + bh.y, 0.f);
    ah.z += fmaxf(w*sh.z + bh.z, 0.f); ah.w += fmaxf(w*sh.w + bh.w, 0.f);
    ai.x += fmaxf(w*si.x + bi.x, 0.f); ai.y += fmaxf(w*si.y + bi.y, 0.f);
    ai.z += fmaxf(w*si.z + bi.z, 0.f); ai.w += fmaxf(w*si.w + bi.w, 0.f);
  }
  for (int q=ch; q<Tn; q+=PCH){
    float4 z = *(const float4*)&d_zr[((size_t)b*NC + q)*HD + c*4];
    fma4(ac,1.f,z);
  }
  float* pp = d_pp + ((size_t)(b*PCH + ch)*3)*HD;
  *(float4*)&pp[0*HD + c*4] = ah;
  *(float4*)&pp[1*HD + c*4] = ac;
  *(float4*)&pp[2*HD + c*4] = ai;
}

// -------- pool finish + gates + classifier (fused) ------------------------------------
__global__ void k_finish_cls(const float* __restrict__ b_c,
                             const float* gwh, const float* gbh, const float* gwc,
                             const float* gbc, const float* gwi, const float* gbi,
                             const float* __restrict__ Wc, const float* __restrict__ bcls,
                             float* __restrict__ out){
  __shared__ float sr[HD];
  __shared__ float sres[HD];
  int b = blockIdx.x, d = threadIdx.x;
  int actn = d_actn[b], Tn = d_Tn[b];
  float ah=0.f, ac=0.f, ai=0.f;
  for (int ch=0; ch<PCH; ch++){
    const float* pp = d_pp + ((size_t)(b*PCH + ch)*3)*HD;
    ah += pp[0*HD+d];
    ac += pp[1*HD+d];
    ai += pp[2*HD+d];
  }
  ac += (float)(actn - Tn) * fmaxf(b_c[d], 0.f);
  float denom = fmaxf((float)actn, 1.f);
  float eh = ah/denom, ec = ac/denom, ei = ai/denom;
  d_eh[b*HD+d] = eh; d_ec[b*HD+d] = ec; d_ei[b*HD+d] = ei;
  float sh, sc, si;
  sr[d] = eh*gwh[d]; __syncthreads();
  for (int s=HD/2; s>0; s>>=1){ if (d<s) sr[d]+=sr[d+s]; __syncthreads(); }
  sh = sr[0]; __syncthreads();
  sr[d] = ec*gwc[d]; __syncthreads();
  for (int s=HD/2; s>0; s>>=1){ if (d<s) sr[d]+=sr[d+s]; __syncthreads(); }
  sc = sr[0]; __syncthreads();
  sr[d] = ei*gwi[d]; __syncthreads();
  for (int s=HD/2; s>0; s>>=1){ if (d<s) sr[d]+=sr[d+s]; __syncthreads(); }
  si = sr[0];
  float gh = 1.f/(1.f+expf(-(sh+gbh[0])));
  float gc = 1.f/(1.f+expf(-(sc+gbc[0])));
  float gi = 1.f/(1.f+expf(-(si+gbi[0])));
  float rv = gh*eh + gc*ec + gi*ei;
  sres[d] = rv;
  __syncthreads();
  for (int o=d; o<NOUT; o+=HD){
    float acc = bcls[o];
    for (int k=0; k<HD; k++) acc += sres[k]*Wc[(size_t)k*NOUT + o];
    out[(size_t)b*NOUT + o] = acc;
  }
}

// -------- InfoNCE loss (single block) --------------------------------------------------
__global__ void k_nce(float* __restrict__ out, int out_size){
  __shared__ float snorm[48];
  __shared__ float sE[256];
  int tid = threadIdx.x, wid = tid>>5, lane = tid&31;
  for (int row=wid; row<48; row+=8){
    const float* base = (row<16) ? (d_eh + row*HD)
                      : (row<32) ? (d_ec + (row-16)*HD)
                                 : (d_ei + (row-32)*HD);
    float s = 0.f;
    for (int d=lane; d<HD; d+=32){ float v = base[d]; s += v*v; }
    s = warp_sum(s);
    if (lane==0) snorm[row] = fmaxf(sqrtf(s), EPSF);
  }
  __syncthreads();
  float total = 0.f;
  for (int pair=0; pair<2; pair++){
    const float* Bm = pair ? d_ei : d_ec;
    int boff = pair ? 32 : 16;
    for (int idx=wid; idx<256; idx+=8){
      int i = idx>>4, j = idx&15;
      const float* a  = d_eh + i*HD;
      const float* bb = Bm   + j*HD;
      float s = 0.f;
      for (int d=lane; d<HD; d+=32) s += a[d]*bb[d];
      s = warp_sum(s);
      if (lane==0) sE[idx] = expf(s / (snorm[i]*snorm[boff+j]*0.4f));
    }
    __syncthreads();
    if (tid==0){
      float l = 0.f;
      for (int i=0;i<16;i++){
        float neg = 0.f;
        for (int j=0;j<16;j++) neg += sE[i*16+j];
        float pos = sE[i*16+i];
        l += -logf(pos/(neg + 1e-8f) + 1e-8f);
      }
      total += l/16.f;
    }
    __syncthreads();
  }
  if (tid==0 && out_size > NB*NOUT) out[NB*NOUT] = total;
}

// ==================================================================================
static cudaStream_t g_s1 = 0, g_s2 = 0, g_s3 = 0;
static cudaEvent_t  g_evR = 0, g_evB = 0, g_evC1 = 0, g_evC2 = 0;
static cudaEvent_t  g_evD = 0, g_evS1 = 0, g_evM1 = 0, g_evM2 = 0;

extern "C" void kernel_launch(void* const* d_in, const int* in_sizes, int n_in,
                              void* d_out, int out_size){
  (void)in_sizes; (void)n_in;
  const float* code_x = (const float*)d_in[0];
  const int*   lens   = (const int*)  d_in[1];
  const float* emb    = (const float*)d_in[2];
  const float* adj    = (const float*)d_in[3];
  const float* ln_g   = (const float*)d_in[4];
  const float* ln_b   = (const float*)d_in[5];
  const float* W_h    = (const float*)d_in[6];
  const float* b_h    = (const float*)d_in[7];
  const float* W_c    = (const float*)d_in[8];
  const float* b_c    = (const float*)d_in[9];
  const float* W_i    = (const float*)d_in[10];
  const float* b_i    = (const float*)d_in[11];
  const float* gw_h   = (const float*)d_in[12];
  const float* gb_h   = (const float*)d_in[13];
  const float* gw_c   = (const float*)d_in[14];
  const float* gb_c   = (const float*)d_in[15];
  const float* gw_i   = (const float*)d_in[16];
  const float* gb_i   = (const float*)d_in[17];
  const float* W_cls  = (const float*)d_in[18];
  const float* b_cls  = (const float*)d_in[19];
  float* out = (float*)d_out;

  if (!g_s1){
    cudaStreamCreateWithFlags(&g_s1, cudaStreamNonBlocking);
    cudaStreamCreateWithFlags(&g_s2, cudaStreamNonBlocking);
    cudaStreamCreateWithFlags(&g_s3, cudaStreamNonBlocking);
    cudaEventCreateWithFlags(&g_evR,  cudaEventDisableTiming);
    cudaEventCreateWithFlags(&g_evB,  cudaEventDisableTiming);
    cudaEventCreateWithFlags(&g_evC1, cudaEventDisableTiming);
    cudaEventCreateWithFlags(&g_evC2, cudaEventDisableTiming);
    cudaEventCreateWithFlags(&g_evD,  cudaEventDisableTiming);
    cudaEventCreateWithFlags(&g_evS1, cudaEventDisableTiming);
    cudaEventCreateWithFlags(&g_evM1, cudaEventDisableTiming);
    cudaEventCreateWithFlags(&g_evM2, cudaEventDisableTiming);
  }

  // fork
  cudaEventRecord(g_evR, 0);
  cudaStreamWaitEvent(g_s1, g_evR, 0);
  cudaStreamWaitEvent(g_s2, g_evR, 0);
  cudaStreamWaitEvent(g_s3, g_evR, 0);

  // ---- branch B (s1): dual emb GEMM ----
  k_gemm2<<<NC/16, 256, 0, g_s1>>>(emb, W_h, W_c);
  cudaEventRecord(g_evB, g_s1);

  // ---- branch C (s2 + s3): per-patient structure, then causal passes ----
  k_masks_compact<<<NB, 1024, 0, g_s2>>>(code_x, lens);
  cudaEventRecord(g_evC1, g_s2);
  k_degrees<<<dim3(NB, 16, 2), 256, 0, g_s2>>>();
  cudaEventRecord(g_evD, g_s2);

  // s3: multi-bit pass1 (needs degrees + EWc only) -- overlaps kV1/kF1s
  cudaStreamWaitEvent(g_s3, g_evD, 0);
  cudaStreamWaitEvent(g_s3, g_evB, 0);
  kF1m<<<dim3(NB, 32), 256, 0, g_s3>>>();
  cudaEventRecord(g_evM1, g_s3);

  // s2: V1 + single-bit pass1
  cudaStreamWaitEvent(g_s2, g_evB, 0);
  kV1 <<<dim3(NB, EV-1), 256, 0, g_s2>>>(lens);
  kF1s<<<dim3(NB, (NC + RPB - 1)/RPB), 256, 0, g_s2>>>();
  cudaEventRecord(g_evS1, g_s2);

  // s3: multi-bit pass2 (needs full yw) -- overlaps kW2/kF2s
  cudaStreamWaitEvent(g_s3, g_evS1, 0);
  kF2m<<<dim3(NB, 32), 256, 0, g_s3>>>(b_c);
  cudaEventRecord(g_evM2, g_s3);

  // s2: W2 (needs full yw) + single-bit pass2
  cudaStreamWaitEvent(g_s2, g_evM1, 0);
  kW2 <<<dim3(NB, EV-1), 256, 0, g_s2>>>(lens);
  kF2s<<<dim3(NB, (NC + RPB - 1)/RPB), 256, 0, g_s2>>>(b_c);
  cudaStreamWaitEvent(g_s2, g_evM2, 0);
  cudaEventRecord(g_evC2, g_s2);

  // ---- branch A (stream 0): adj structure + icd chain ----
  k_zero<<<2, 1024>>>();
  k_csr_scat<<<(NC + 31)/32, 1024>>>(adj);
  k_spmm_rows<<<NC/4, 128>>>(emb, 0);
  k_spmm_cols_ln<<<NC/4, 128>>>(ln_g, ln_b);
  k_spmm_rows<<<NC/4, 128>>>(emb, 1);
  k_spmm_cols_ln<<<NC/4, 128>>>(ln_g, ln_b);
  k_spmm_rows<<<NC/4, 128>>>(emb, 1);
  k_spmm_cols_ln<<<NC/4, 128>>>(ln_g, ln_b);
  k_gemm1<<<NC/16, 256>>>(W_i);   // icd @ W_i

  // ---- join ----
  cudaStreamWaitEvent(0, g_evB, 0);      // EWh for tprime
  cudaStreamWaitEvent(0, g_evC1, 0);     // vl/vlen/Dvinv for tprime
  k_tprime<<<dim3(NB, EV), 64>>>();
  cudaStreamWaitEvent(0, g_evC2, 0);     // zr from pass2
  k_poolpart<<<dim3(NB, PCH), 64>>>(b_h, b_i);
  k_finish_cls<<<NB, HD>>>(b_c, gw_h, gb_h, gw_c, gb_c, gw_i, gb_i, W_cls, b_cls, out);
  k_nce<<<1, 256>>>(out, out_size);
}

// round 17
// speedup vs baseline: 1.4541x; 1.4541x over previous
#include <cuda_runtime.h>
#include <math.h>

#define NC   2000   // codes
#define EV   32     // visits
#define DD   128    // embedding dim
#define HD   256    // hidden dim
#define NOUT 1000
#define NB   16     // batch
#define PAD  128    // max nnz per adj row/col
#define VCAP 128    // max codes per visit
#define PCH  16     // pool partial chunks
#define RPB  8      // rows per block in pass kernels
#define QT2  256    // hit-list tile size
#define EPSF 1e-12f

// ---------------- scratch (device globals; no allocation) ----------------
static __device__ float d_icd[NC*DD];
static __device__ float d_buf[NC*DD];
static __device__ float d_EWh[NC*HD];
static __device__ float d_EWc[NC*HD];
static __device__ float d_IWi[NC*HD];

static __device__ int   d_rowcnt[NC];
static __device__ int   d_rowidx[NC*PAD];
static __device__ int   d_colcnt[NC];
static __device__ int   d_colidx[NC*PAD];

static __device__ unsigned d_vmask[NB*NC];
static __device__ unsigned d_smask[NB*NC];
static __device__ unsigned d_dmask[NB*NC];
static __device__ float d_Dvinv[NB*NC];
static __device__ int d_act[NB*NC];  static __device__ int d_actn[NB];
static __device__ int d_Sl[NB*NC];   static __device__ int d_Sn[NB];
static __device__ int d_Tl[NB*NC];   static __device__ int d_Tn[NB];
static __device__ int d_Sml[NB*NC];  static __device__ int d_Smn[NB];  // multi-bit S codes
static __device__ int d_Tml[NB*NC];  static __device__ int d_Tmn[NB];  // multi-bit T codes
static __device__ int d_spos[NB*NC];          // code -> S position
static __device__ int d_tpos[NB*NC];          // code -> T position
static __device__ int d_vl[NB*EV*VCAP];
static __device__ int d_vlen[NB*EV];
static __device__ unsigned d_Tdm[NB*NC];      // position-indexed T: dmask
static __device__ float    d_Tcv[NB*NC];      // position-indexed T: cinv
static __device__ unsigned d_Ssm[NB*NC];      // position-indexed S: smask
static __device__ float    d_Srv[NB*NC];      // position-indexed S: rinv
static __device__ float d_cinvc[NB*NC];       // code-indexed cinv (T codes)
static __device__ float d_rinvc[NB*NC];       // code-indexed rinv (S codes)
static __device__ float d_V1[(size_t)NB*EV*HD];
static __device__ float d_W2[(size_t)NB*EV*HD];
static __device__ float d_tph[NB*EV*HD];
static __device__ float d_tpi[NB*EV*HD];
static __device__ float d_yw[(size_t)NB*NC*HD];
static __device__ float d_zr[(size_t)NB*NC*HD];
static __device__ float d_pp[NB*PCH*3*HD];
static __device__ float d_eh[NB*HD], d_ec[NB*HD], d_ei[NB*HD];

__device__ __forceinline__ float warp_sum(float v){
  #pragma unroll
  for (int o=16;o>0;o>>=1) v += __shfl_down_sync(0xffffffffu, v, o);
  return v;
}
__device__ __forceinline__ float warp_allsum(float v){
  #pragma unroll
  for (int o=16;o>0;o>>=1) v += __shfl_xor_sync(0xffffffffu, v, o);
  return v;
}
__device__ __forceinline__ void fma4(float4& a, float s, const float4& e){
  a.x += s*e.x; a.y += s*e.y; a.z += s*e.z; a.w += s*e.w;
}

// ---------------- zero colcnt ----------------------------------------------------
__global__ void k_zero(){
  int t = blockIdx.x*blockDim.x + threadIdx.x;
  if (t < NC) d_colcnt[t] = 0;
}

// ---------------- CSR of adj + CSC scatter (warp per row) -------------------------
__global__ void k_csr_scat(const float* __restrict__ adj){
  int w = threadIdx.x >> 5, lane = threadIdx.x & 31;
  int r = blockIdx.x*32 + w;
  if (r >= NC) return;
  int cnt = 0;
  for (int jt=0; jt<NC; jt+=256){
    float v[8];
    #pragma unroll
    for (int u=0; u<8; u++){
      int j = jt + u*32 + lane;
      v[u] = (j < NC) ? adj[(size_t)r*NC + j] : 0.f;
    }
    #pragma unroll
    for (int u=0; u<8; u++){
      unsigned m = __ballot_sync(0xffffffffu, v[u] != 0.f);
      if (v[u] != 0.f){
        int pos = cnt + __popc(m & ((1u<<lane)-1u));
        if (pos < PAD) d_rowidx[r*PAD+pos] = jt + u*32 + lane;
      }
      cnt += __popc(m);
    }
  }
  if (cnt > PAD) cnt = PAD;
  if (lane == 0) d_rowcnt[r] = cnt;
  for (int p=lane; p<cnt; p+=32){
    int j = d_rowidx[r*PAD+p];
    int pos = atomicAdd(&d_colcnt[j], 1);
    if (pos < PAD) d_colidx[j*PAD+pos] = r;
  }
}

// ---------------- sparse y = adj @ x (warp per row, float4, unrolled) -------------
__global__ void k_spmm_rows(const float* __restrict__ emb, int use_icd){
  const float* src = use_icd ? d_icd : emb;
  int i = blockIdx.x*4 + (threadIdx.x>>5);
  int c = threadIdx.x & 31;
  int cnt = d_rowcnt[i];
  const int* idx = d_rowidx + i*PAD;
  float4 acc = make_float4(0.f,0.f,0.f,0.f);
  int p = 0;
  for (; p+4<=cnt; p+=4){
    int j0=idx[p], j1=idx[p+1], j2=idx[p+2], j3=idx[p+3];
    float4 v0 = *(const float4*)&src[(size_t)j0*DD + c*4];
    float4 v1 = *(const float4*)&src[(size_t)j1*DD + c*4];
    float4 v2 = *(const float4*)&src[(size_t)j2*DD + c*4];
    float4 v3 = *(const float4*)&src[(size_t)j3*DD + c*4];
    fma4(acc,1.f,v0); fma4(acc,1.f,v1); fma4(acc,1.f,v2); fma4(acc,1.f,v3);
  }
  for (; p<cnt; p++){
    float4 v = *(const float4*)&src[(size_t)idx[p]*DD + c*4];
    fma4(acc,1.f,v);
  }
  *(float4*)&d_buf[i*DD + c*4] = acc;
}

// ---------------- x = LN(adj.T @ buf) ----------------------------------------------
__global__ void k_spmm_cols_ln(const float* __restrict__ g, const float* __restrict__ b){
  int j = blockIdx.x*4 + (threadIdx.x>>5);
  int c = threadIdx.x & 31;
  int cnt = d_colcnt[j]; if (cnt > PAD) cnt = PAD;
  const int* idx = d_colidx + j*PAD;
  float4 acc = make_float4(0.f,0.f,0.f,0.f);
  int p = 0;
  for (; p+4<=cnt; p+=4){
    int j0=idx[p], j1=idx[p+1], j2=idx[p+2], j3=idx[p+3];
    float4 v0 = *(const float4*)&d_buf[(size_t)j0*DD + c*4];
    float4 v1 = *(const float4*)&d_buf[(size_t)j1*DD + c*4];
    float4 v2 = *(const float4*)&d_buf[(size_t)j2*DD + c*4];
    float4 v3 = *(const float4*)&d_buf[(size_t)j3*DD + c*4];
    fma4(acc,1.f,v0); fma4(acc,1.f,v1); fma4(acc,1.f,v2); fma4(acc,1.f,v3);
  }
  for (; p<cnt; p++){
    float4 v = *(const float4*)&d_buf[(size_t)idx[p]*DD + c*4];
    fma4(acc,1.f,v);
  }
  float m = warp_allsum(acc.x+acc.y+acc.z+acc.w) / (float)DD;
  float4 df = make_float4(acc.x-m, acc.y-m, acc.z-m, acc.w-m);
  float var = warp_allsum(df.x*df.x + df.y*df.y + df.z*df.z + df.w*df.w) / (float)DD;
  float r = rsqrtf(var + 1e-5f);
  float4 gg = *(const float4*)&g[c*4];
  float4 bb = *(const float4*)&b[c*4];
  float4 o;
  o.x = df.x*r*gg.x + bb.x; o.y = df.y*r*gg.y + bb.y;
  o.z = df.z*r*gg.z + bb.z; o.w = df.w*r*gg.w + bb.w;
  *(float4*)&d_icd[j*DD + c*4] = o;
}

// ---------------- dual GEMM: EWh = X@Wh, EWc = X@Wc (register-tiled) --------------
__global__ void k_gemm2(const float* __restrict__ X, const float* __restrict__ Wh,
                        const float* __restrict__ Wc){
  __shared__ float xs[16][DD];
  int r0 = blockIdx.x*16;
  int tid = threadIdx.x;
  for (int t=tid; t<16*DD; t+=256)
    xs[t>>7][t&127] = X[(size_t)(r0 + (t>>7))*DD + (t&127)];
  __syncthreads();
  int rg = tid>>6;
  int c4 = (tid&63)<<2;
  float4 ah0=make_float4(0,0,0,0), ah1=ah0, ah2=ah0, ah3=ah0;
  float4 ac0=ah0, ac1=ah0, ac2=ah0, ac3=ah0;
  const float* xrow = &xs[rg*4][0];
  for (int k=0; k<DD; k++){
    float4 wh = *(const float4*)&Wh[(size_t)k*HD + c4];
    float4 wc = *(const float4*)&Wc[(size_t)k*HD + c4];
    float x0 = xrow[k], x1 = xrow[DD+k], x2 = xrow[2*DD+k], x3 = xrow[3*DD+k];
    fma4(ah0,x0,wh); fma4(ah1,x1,wh); fma4(ah2,x2,wh); fma4(ah3,x3,wh);
    fma4(ac0,x0,wc); fma4(ac1,x1,wc); fma4(ac2,x2,wc); fma4(ac3,x3,wc);
  }
  int rbase = r0 + rg*4;
  *(float4*)&d_EWh[(size_t)(rbase+0)*HD + c4] = ah0;
  *(float4*)&d_EWh[(size_t)(rbase+1)*HD + c4] = ah1;
  *(float4*)&d_EWh[(size_t)(rbase+2)*HD + c4] = ah2;
  *(float4*)&d_EWh[(size_t)(rbase+3)*HD + c4] = ah3;
  *(float4*)&d_EWc[(size_t)(rbase+0)*HD + c4] = ac0;
  *(float4*)&d_EWc[(size_t)(rbase+1)*HD + c4] = ac1;
  *(float4*)&d_EWc[(size_t)(rbase+2)*HD + c4] = ac2;
  *(float4*)&d_EWc[(size_t)(rbase+3)*HD + c4] = ac3;
}

// ---------------- single GEMM: IWi = icd @ Wi -------------------------------------
__global__ void k_gemm1(const float* __restrict__ Wi){
  __shared__ float xs[16][DD];
  int r0 = blockIdx.x*16;
  int tid = threadIdx.x;
  for (int t=tid; t<16*DD; t+=256)
    xs[t>>7][t&127] = d_icd[(size_t)(r0 + (t>>7))*DD + (t&127)];
  __syncthreads();
  int rg = tid>>6;
  int c4 = (tid&63)<<2;
  float4 a0=make_float4(0,0,0,0), a1=a0, a2=a0, a3=a0;
  const float* xrow = &xs[rg*4][0];
  for (int k=0; k<DD; k++){
    float4 w = *(const float4*)&Wi[(size_t)k*HD + c4];
    float x0 = xrow[k], x1 = xrow[DD+k], x2 = xrow[2*DD+k], x3 = xrow[3*DD+k];
    fma4(a0,x0,w); fma4(a1,x1,w); fma4(a2,x2,w); fma4(a3,x3,w);
  }
  int rbase = r0 + rg*4;
  *(float4*)&d_IWi[(size_t)(rbase+0)*HD + c4] = a0;
  *(float4*)&d_IWi[(size_t)(rbase+1)*HD + c4] = a1;
  *(float4*)&d_IWi[(size_t)(rbase+2)*HD + c4] = a2;
  *(float4*)&d_IWi[(size_t)(rbase+3)*HD + c4] = a3;
}

// ---------------- fused masks + compactions (block per patient) --------------------
__global__ void k_masks_compact(const float* __restrict__ cx, const int* __restrict__ lens){
  __shared__ unsigned svm[NC];
  int b = blockIdx.x;
  int tid = threadIdx.x;
  int len = lens[b];
  unsigned lowm = (1u << (len-1)) - 1u;
  const float* cxb = cx + (size_t)b*EV*NC;
  for (int i=tid; i<NC; i+=1024){
    unsigned m = 0; int c = 0;
    for (int e=0; e<len; e++){
      if (cxb[(size_t)e*NC + i] != 0.f){ m |= (1u<<e); c++; }
    }
    svm[i] = m;
    d_vmask[b*NC+i] = m;
    d_Dvinv[b*NC+i] = rsqrtf(fmaxf((float)c, EPSF));
    d_smask[b*NC+i] = m & lowm;
    d_dmask[b*NC+i] = (m >> 1) & lowm;
  }
  __syncthreads();
  int w = tid>>5, lane = tid&31;
  unsigned ltm = (1u<<lane)-1u;
  {
    int cnt = 0;
    for (int base=0; base<NC; base+=32){
      int i = base + lane;
      bool v = (i<NC) && ((svm[i] >> w) & 1u);
      unsigned mm = __ballot_sync(0xffffffffu, v);
      if (v){
        int pos = cnt + __popc(mm & ltm);
        if (pos < VCAP) d_vl[((size_t)b*EV + w)*VCAP + pos] = i;
      }
      cnt += __popc(mm);
    }
    if (lane == 0) d_vlen[b*EV + w] = (cnt < VCAP) ? cnt : VCAP;
  }
  if (w < 5){
    int cnt = 0;
    for (int base=0; base<NC; base+=32){
      int i = base + lane;
      bool v = false;
      if (i < NC){
        unsigned m = svm[i];
        unsigned sm = m & lowm;
        unsigned dm = (m>>1) & lowm;
        if      (w==0) v = (m != 0u);
        else if (w==1) v = (sm != 0u);
        else if (w==2) v = (dm != 0u);
        else if (w==3) v = (__popc(sm) >= 2);
        else           v = (__popc(dm) >= 2);
      }
      unsigned mm = __ballot_sync(0xffffffffu, v);
      if (v){
        int pos = cnt + __popc(mm & ltm);
        if      (w==0) d_act[b*NC+pos] = i;
        else if (w==1){ d_Sl[b*NC+pos] = i; d_spos[b*NC+i] = pos; }
        else if (w==2){ d_Tl[b*NC+pos] = i; d_tpos[b*NC+i] = pos; }
        else if (w==3) d_Sml[b*NC+pos] = i;
        else           d_Tml[b*NC+pos] = i;
      }
      cnt += __popc(mm);
    }
    if (lane == 0){
      if      (w==0) d_actn[b] = cnt;
      else if (w==1) d_Sn[b]   = cnt;
      else if (w==2) d_Tn[b]   = cnt;
      else if (w==3) d_Smn[b]  = cnt;
      else           d_Tmn[b]  = cnt;
    }
  }
}

// -------- tph[e] only (hidden early on s1) ---------------------------------------------
__global__ void k_tprime_h(){
  int b = blockIdx.x, e = blockIdx.y, c = threadIdx.x;
  int n = d_vlen[b*EV + e];
  const int* vl = d_vl + ((size_t)b*EV + e)*VCAP;
  float4 ah = make_float4(0.f,0.f,0.f,0.f);
  int k = 0;
  for (; k+4<=n; k+=4){
    int i0 = vl[k], i1 = vl[k+1], i2 = vl[k+2], i3 = vl[k+3];
    float w0 = d_Dvinv[b*NC+i0], w1 = d_Dvinv[b*NC+i1];
    float w2 = d_Dvinv[b*NC+i2], w3 = d_Dvinv[b*NC+i3];
    float4 h0 = *(const float4*)&d_EWh[(size_t)i0*HD + c*4];
    float4 h1 = *(const float4*)&d_EWh[(size_t)i1*HD + c*4];
    float4 h2 = *(const float4*)&d_EWh[(size_t)i2*HD + c*4];
    float4 h3 = *(const float4*)&d_EWh[(size_t)i3*HD + c*4];
    fma4(ah,w0,h0); fma4(ah,w1,h1); fma4(ah,w2,h2); fma4(ah,w3,h3);
  }
  for (; k<n; k++){
    int i = vl[k];
    float w = d_Dvinv[b*NC+i];
    float4 h = *(const float4*)&d_EWh[(size_t)i*HD + c*4];
    fma4(ah,w,h);
  }
  float inv = 1.f / fmaxf((float)n, EPSF);
  ah.x*=inv; ah.y*=inv; ah.z*=inv; ah.w*=inv;
  *(float4*)&d_tph[((size_t)b*EV+e)*HD + c*4] = ah;
}

// -------- tpi[e] only (tail, after gemm1) ----------------------------------------------
__global__ void k_tprime_i(){
  int b = blockIdx.x, e = blockIdx.y, c = threadIdx.x;
  int n = d_vlen[b*EV + e];
  const int* vl = d_vl + ((size_t)b*EV + e)*VCAP;
  float4 ai = make_float4(0.f,0.f,0.f,0.f);
  int k = 0;
  for (; k+4<=n; k+=4){
    int i0 = vl[k], i1 = vl[k+1], i2 = vl[k+2], i3 = vl[k+3];
    float w0 = d_Dvinv[b*NC+i0], w1 = d_Dvinv[b*NC+i1];
    float w2 = d_Dvinv[b*NC+i2], w3 = d_Dvinv[b*NC+i3];
    float4 v0 = *(const float4*)&d_IWi[(size_t)i0*HD + c*4];
    float4 v1 = *(const float4*)&d_IWi[(size_t)i1*HD + c*4];
    float4 v2 = *(const float4*)&d_IWi[(size_t)i2*HD + c*4];
    float4 v3 = *(const float4*)&d_IWi[(size_t)i3*HD + c*4];
    fma4(ai,w0,v0); fma4(ai,w1,v1); fma4(ai,w2,v2); fma4(ai,w3,v3);
  }
  for (; k<n; k++){
    int i = vl[k];
    float w = d_Dvinv[b*NC+i];
    float4 v = *(const float4*)&d_IWi[(size_t)i*HD + c*4];
    fma4(ai,w,v);
  }
  float inv = 1.f / fmaxf((float)n, EPSF);
  ai.x*=inv; ai.y*=inv; ai.z*=inv; ai.w*=inv;
  *(float4*)&d_tpi[((size_t)b*EV+e)*HD + c*4] = ai;
}

// -------- degrees of A + metadata (position- and code-indexed) -----------------------
__global__ void k_degrees(){
  __shared__ int      sIdx[NC];
  __shared__ unsigned sMsk[NC];
  int b = blockIdx.x, z = blockIdx.z;
  int Rn = z ? d_Tn[b] : d_Sn[b];
  int Cn = z ? d_Sn[b] : d_Tn[b];
  const int* rl = z ? (d_Tl + b*NC) : (d_Sl + b*NC);
  const int* cl = z ? (d_Sl + b*NC) : (d_Tl + b*NC);
  for (int q=threadIdx.x; q<Cn; q+=blockDim.x){
    int j = cl[q];
    sIdx[q] = j;
    sMsk[q] = z ? d_smask[b*NC+j] : d_dmask[b*NC+j];
  }
  __syncthreads();
  for (int p = blockIdx.y*blockDim.x + threadIdx.x; p < Rn; p += gridDim.y*blockDim.x){
    int i = rl[p];
    unsigned m = z ? d_dmask[b*NC+i] : d_smask[b*NC+i];
    float s = 0.f;
    for (int q=0; q<Cn; q++)
      s += ((m & sMsk[q]) && (sIdx[q] != i)) ? 1.f : 0.f;
    float inv = rsqrtf(fmaxf(s, EPSF));
    if (z){ d_Tdm[b*NC+p] = m; d_Tcv[b*NC+p] = inv; d_cinvc[b*NC+i] = inv; }
    else  { d_Ssm[b*NC+p] = m; d_Srv[b*NC+p] = inv; d_rinvc[b*NC+i] = inv; }
  }
}

// -------- V1[t] = sum_{j in visit t+1} cinv_j * EWc[j]  (256 thr, k-slice x4) ---------
__global__ void kV1(const int* __restrict__ lens){
  __shared__ float red[4][HD];
  int b = blockIdx.x, t = blockIdx.y;
  if (t >= lens[b]-1) return;
  int e = t+1;
  int n = d_vlen[b*EV + e];
  const int* vl = d_vl + ((size_t)b*EV + e)*VCAP;
  int s = threadIdx.x>>6, c = threadIdx.x&63;
  float4 acc = make_float4(0.f,0.f,0.f,0.f);
  for (int k=s; k<n; k+=4){
    int j = vl[k];
    float v = d_cinvc[b*NC+j];
    float4 ew = *(const float4*)&d_EWc[(size_t)j*HD + c*4];
    fma4(acc,v,ew);
  }
  *(float4*)&red[s][c*4] = acc;
  __syncthreads();
  if (s == 0){
    float4 a = acc;
    fma4(a,1.f,*(const float4*)&red[1][c*4]);
    fma4(a,1.f,*(const float4*)&red[2][c*4]);
    fma4(a,1.f,*(const float4*)&red[3][c*4]);
    *(float4*)&d_V1[((size_t)b*EV+t)*HD + c*4] = a;
  }
}

// -------- pass1 single-bit rows: yw[p] = rinv*(V1[t] - self) ---------------------------
__global__ void kF1s(){
  int b = blockIdx.x;
  int Sn = d_Sn[b];
  int p0 = blockIdx.y*RPB;
  if (p0 >= Sn) return;
  int g = threadIdx.x>>6, c = threadIdx.x&63;
  #pragma unroll
  for (int pick=0; pick<2; pick++){
    int p = p0 + g + pick*4;
    if (p >= Sn) break;
    unsigned sm = d_Ssm[b*NC+p];
    if (__popc(sm) != 1) continue;
    int code = d_Sl[b*NC+p];
    int t = __ffs(sm) - 1;
    float4 a = *(const float4*)&d_V1[((size_t)b*EV+t)*HD + c*4];
    if (d_dmask[b*NC+code] & sm){
      float cv = d_cinvc[b*NC+code];
      float4 e = *(const float4*)&d_EWc[(size_t)code*HD + c*4];
      a.x -= cv*e.x; a.y -= cv*e.y; a.z -= cv*e.z; a.w -= cv*e.w;
    }
    float rv = d_Srv[b*NC+p];
    a.x*=rv; a.y*=rv; a.z*=rv; a.w*=rv;
    *(float4*)&d_yw[((size_t)b*NC + p)*HD + c*4] = a;
  }
}

// -------- pass1 multi-bit rows (hit lists over full T table) ---------------------------
__global__ void kF1m(){
  __shared__ int      sTi[NC];
  __shared__ unsigned sTd[NC];
  __shared__ float    sTc[NC];
  __shared__ int   hlc[RPB][QT2];
  __shared__ float hlv[RPB][QT2];
  __shared__ int   hn[RPB];
  int b = blockIdx.x;
  int Smn = d_Smn[b];
  int p0 = blockIdx.y*RPB;
  if (p0 >= Smn) return;
  int Tn = d_Tn[b];
  int tid = threadIdx.x, w = tid>>5, lane = tid&31;
  unsigned ltm = (1u<<lane)-1u;
  for (int q=tid; q<Tn; q+=256){
    sTi[q] = d_Tl[b*NC+q];
    sTd[q] = d_Tdm[b*NC+q];
    sTc[q] = d_Tcv[b*NC+q];
  }
  int nr = Smn - p0; if (nr > RPB) nr = RPB;
  int code = 0; unsigned sm = 0;
  if (w < nr){ code = d_Sml[b*NC+p0+w]; sm = d_smask[b*NC+code]; }
  int g = tid>>6, c = tid&63;
  float4 acc0 = make_float4(0.f,0.f,0.f,0.f), acc1 = acc0;
  __syncthreads();
  for (int q0=0; q0<Tn; q0+=QT2){
    int qe = q0+QT2; if (qe > Tn) qe = Tn;
    if (w < nr){
      int cnt = 0;
      for (int qb=q0; qb<qe; qb+=32){
        int q = qb + lane;
        bool hit = (q < qe) && (sm & sTd[q]) && (sTi[q] != code);
        unsigned mm = __ballot_sync(0xffffffffu, hit);
        if (hit){
          int pos = cnt + __popc(mm & ltm);
          hlc[w][pos] = sTi[q]; hlv[w][pos] = sTc[q];
        }
        cnt += __popc(mm);
      }
      if (lane == 0) hn[w] = cnt;
    }
    __syncthreads();
    if (g < nr){
      int n = hn[g];
      for (int k=0; k<n; k++){
        int j = hlc[g][k]; float v = hlv[g][k];
        float4 e = *(const float4*)&d_EWc[(size_t)j*HD + c*4];
        fma4(acc0,v,e);
      }
    }
    if (g+4 < nr){
      int n = hn[g+4];
      for (int k=0; k<n; k++){
        int j = hlc[g+4][k]; float v = hlv[g+4][k];
        float4 e = *(const float4*)&d_EWc[(size_t)j*HD + c*4];
        fma4(acc1,v,e);
      }
    }
    __syncthreads();
  }
  #pragma unroll
  for (int pick=0; pick<2; pick++){
    int r = g + pick*4;
    if (r >= nr) break;
    float4 a = pick ? acc1 : acc0;
    int cd = d_Sml[b*NC+p0+r];
    int p = d_spos[b*NC+cd];
    float rv = d_rinvc[b*NC+cd];
    a.x*=rv; a.y*=rv; a.z*=rv; a.w*=rv;
    *(float4*)&d_yw[((size_t)b*NC + p)*HD + c*4] = a;
  }
}

// -------- W2[t] = sum_{i in visit t} rinv_i * yw[spos_i]  (256 thr, k-slice x4) -------
__global__ void kW2(const int* __restrict__ lens){
  __shared__ float red[4][HD];
  int b = blockIdx.x, t = blockIdx.y;
  if (t >= lens[b]-1) return;
  int n = d_vlen[b*EV + t];
  const int* vl = d_vl + ((size_t)b*EV + t)*VCAP;
  int s = threadIdx.x>>6, c = threadIdx.x&63;
  float4 acc = make_float4(0.f,0.f,0.f,0.f);
  for (int k=s; k<n; k+=4){
    int i = vl[k];
    float v = d_rinvc[b*NC+i];
    int sp = d_spos[b*NC+i];
    float4 e = *(const float4*)&d_yw[((size_t)b*NC + sp)*HD + c*4];
    fma4(acc,v,e);
  }
  *(float4*)&red[s][c*4] = acc;
  __syncthreads();
  if (s == 0){
    float4 a = acc;
    fma4(a,1.f,*(const float4*)&red[1][c*4]);
    fma4(a,1.f,*(const float4*)&red[2][c*4]);
    fma4(a,1.f,*(const float4*)&red[3][c*4]);
    *(float4*)&d_W2[((size_t)b*EV+t)*HD + c*4] = a;
  }
}

// -------- pass2 single-bit rows: zr[q] = relu(cinv*(W2[t] - self) + b_c) ---------------
__global__ void kF2s(const float* __restrict__ b_c){
  int b = blockIdx.x;
  int Tn = d_Tn[b];
  int q0 = blockIdx.y*RPB;
  if (q0 >= Tn) return;
  int g = threadIdx.x>>6, c = threadIdx.x&63;
  float4 bc = *(const float4*)&b_c[c*4];
  #pragma unroll
  for (int pick=0; pick<2; pick++){
    int q = q0 + g + pick*4;
    if (q >= Tn) break;
    unsigned dm = d_Tdm[b*NC+q];
    if (__popc(dm) != 1) continue;
    int code = d_Tl[b*NC+q];
    int t = __ffs(dm) - 1;
    float4 a = *(const float4*)&d_W2[((size_t)b*EV+t)*HD + c*4];
    unsigned sj = d_smask[b*NC+code];
    if (sj & dm){
      float rvj = d_rinvc[b*NC+code];
      int sp = d_spos[b*NC+code];
      float4 e = *(const float4*)&d_yw[((size_t)b*NC + sp)*HD + c*4];
      a.x -= rvj*e.x; a.y -= rvj*e.y; a.z -= rvj*e.z; a.w -= rvj*e.w;
    }
    float cv = d_Tcv[b*NC+q];
    float4 o;
    o.x = fmaxf(cv*a.x + bc.x, 0.f); o.y = fmaxf(cv*a.y + bc.y, 0.f);
    o.z = fmaxf(cv*a.z + bc.z, 0.f); o.w = fmaxf(cv*a.w + bc.w, 0.f);
    *(float4*)&d_zr[((size_t)b*NC + q)*HD + c*4] = o;
  }
}

// -------- pass2 multi-bit rows (hit lists over full S table) ---------------------------
__global__ void kF2m(const float* __restrict__ b_c){
  __shared__ int      sSi[NC];
  __shared__ unsigned sSs[NC];
  __shared__ float    sSr[NC];
  __shared__ int   hlp[RPB][QT2];
  __shared__ float hlv[RPB][QT2];
  __shared__ int   hn[RPB];
  int b = blockIdx.x;
  int Tmn = d_Tmn[b];
  int q0b = blockIdx.y*RPB;
  if (q0b >= Tmn) return;
  int Sn = d_Sn[b];
  int tid = threadIdx.x, w = tid>>5, lane = tid&31;
  unsigned ltm = (1u<<lane)-1u;
  for (int p=tid; p<Sn; p+=256){
    sSi[p] = d_Sl[b*NC+p];
    sSs[p] = d_Ssm[b*NC+p];
    sSr[p] = d_Srv[b*NC+p];
  }
  int nr = Tmn - q0b; if (nr > RPB) nr = RPB;
  int code = 0; unsigned dm = 0;
  if (w < nr){ code = d_Tml[b*NC+q0b+w]; dm = d_dmask[b*NC+code]; }
  int g = tid>>6, c = tid&63;
  float4 acc0 = make_float4(0.f,0.f,0.f,0.f), acc1 = acc0;
  __syncthreads();
  for (int p0=0; p0<Sn; p0+=QT2){
    int pe = p0+QT2; if (pe > Sn) pe = Sn;
    if (w < nr){
      int cnt = 0;
      for (int pb=p0; pb<pe; pb+=32){
        int p = pb + lane;
        bool hit = (p < pe) && (dm & sSs[p]) && (sSi[p] != code);
        unsigned mm = __ballot_sync(0xffffffffu, hit);
        if (hit){
          int pos = cnt + __popc(mm & ltm);
          hlp[w][pos] = p; hlv[w][pos] = sSr[p];
        }
        cnt += __popc(mm);
      }
      if (lane == 0) hn[w] = cnt;
    }
    __syncthreads();
    if (g < nr){
      int n = hn[g];
      for (int k=0; k<n; k++){
        int p = hlp[g][k]; float v = hlv[g][k];
        float4 e = *(const float4*)&d_yw[((size_t)b*NC + p)*HD + c*4];
        fma4(acc0,v,e);
      }
    }
    if (g+4 < nr){
      int n = hn[g+4];
      for (int k=0; k<n; k++){
        int p = hlp[g+4][k]; float v = hlv[g+4][k];
        float4 e = *(const float4*)&d_yw[((size_t)b*NC + p)*HD + c*4];
        fma4(acc1,v,e);
      }
    }
    __syncthreads();
  }
  float4 bc = *(const float4*)&b_c[c*4];
  #pragma unroll
  for (int pick=0; pick<2; pick++){
    int r = g + pick*4;
    if (r >= nr) break;
    float4 a = pick ? acc1 : acc0;
    int cd = d_Tml[b*NC+q0b+r];
    int q = d_tpos[b*NC+cd];
    float cv = d_cinvc[b*NC+cd];
    float4 o;
    o.x = fmaxf(cv*a.x + bc.x, 0.f); o.y = fmaxf(cv*a.y + bc.y, 0.f);
    o.z = fmaxf(cv*a.z + bc.z, 0.f); o.w = fmaxf(cv*a.w + bc.w, 0.f);
    *(float4*)&d_zr[((size_t)b*NC + q)*HD + c*4] = o;
  }
}

// -------- pooled partials over PCH deterministic chunks (float4, block 64) ----------
__global__ void k_poolpart(const float* __restrict__ b_h, const float* __restrict__ b_i){
  int b = blockIdx.x, ch = blockIdx.y, c = threadIdx.x;
  int actn = d_actn[b], Tn = d_Tn[b];
  float4 bh = *(const float4*)&b_h[c*4];
  float4 bi = *(const float4*)&b_i[c*4];
  float4 ah = make_float4(0.f,0.f,0.f,0.f), ai = ah, ac = ah;
  for (int p=ch; p<actn; p+=PCH){
    int i = d_act[b*NC+p];
    unsigned m = d_vmask[b*NC+i];
    float w = d_Dvinv[b*NC+i];
    float4 sh = make_float4(0.f,0.f,0.f,0.f), si = sh;
    while (m){
      int e = __ffs(m) - 1; m &= (m-1u);
      float4 th = *(const float4*)&d_tph[((size_t)b*EV+e)*HD + c*4];
      float4 ti = *(const float4*)&d_tpi[((size_t)b*EV+e)*HD + c*4];
      fma4(sh,1.f,th); fma4(si,1.f,ti);
    }
    ah.x += fmaxf(w*sh.x + bh.x, 0.f); ah.y += fmaxf(w*sh.y + bh.y, 0.f);
    ah.z += fmaxf(w*sh.z + bh.z, 0.f); ah.w += fmaxf(w*sh.w + bh.w, 0.f);
    ai.x += fmaxf(w*si.x + bi.x, 0.f); ai.y += fmaxf(w*si.y + bi.y, 0.f);
    ai.z += fmaxf(w*si.z + bi.z, 0.f); ai.w += fmaxf(w*si.w + bi.w, 0.f);
  }
  for (int q=ch; q<Tn; q+=PCH){
    float4 z = *(const float4*)&d_zr[((size_t)b*NC + q)*HD + c*4];
    fma4(ac,1.f,z);
  }
  float* pp = d_pp + ((size_t)(b*PCH + ch)*3)*HD;
  *(float4*)&pp[0*HD + c*4] = ah;
  *(float4*)&pp[1*HD + c*4] = ac;
  *(float4*)&pp[2*HD + c*4] = ai;
}

// -------- pool finish + gates + classifier (fused) ------------------------------------
__global__ void k_finish_cls(const float* __restrict__ b_c,
                             const float* gwh, const float* gbh, const float* gwc,
                             const float* gbc, const float* gwi, const float* gbi,
                             const float* __restrict__ Wc, const float* __restrict__ bcls,
                             float* __restrict__ out){
  __shared__ float sr[HD];
  __shared__ float sres[HD];
  int b = blockIdx.x, d = threadIdx.x;
  int actn = d_actn[b], Tn = d_Tn[b];
  float ah=0.f, ac=0.f, ai=0.f;
  for (int ch=0; ch<PCH; ch++){
    const float* pp = d_pp + ((size_t)(b*PCH + ch)*3)*HD;
    ah += pp[0*HD+d];
    ac += pp[1*HD+d];
    ai += pp[2*HD+d];
  }
  ac += (float)(actn - Tn) * fmaxf(b_c[d], 0.f);
  float denom = fmaxf((float)actn, 1.f);
  float eh = ah/denom, ec = ac/denom, ei = ai/denom;
  d_eh[b*HD+d] = eh; d_ec[b*HD+d] = ec; d_ei[b*HD+d] = ei;
  float sh, sc, si;
  sr[d] = eh*gwh[d]; __syncthreads();
  for (int s=HD/2; s>0; s>>=1){ if (d<s) sr[d]+=sr[d+s]; __syncthreads(); }
  sh = sr[0]; __syncthreads();
  sr[d] = ec*gwc[d]; __syncthreads();
  for (int s=HD/2; s>0; s>>=1){ if (d<s) sr[d]+=sr[d+s]; __syncthreads(); }
  sc = sr[0]; __syncthreads();
  sr[d] = ei*gwi[d]; __syncthreads();
  for (int s=HD/2; s>0; s>>=1){ if (d<s) sr[d]+=sr[d+s]; __syncthreads(); }
  si = sr[0];
  float gh = 1.f/(1.f+expf(-(sh+gbh[0])));
  float gc = 1.f/(1.f+expf(-(sc+gbc[0])));
  float gi = 1.f/(1.f+expf(-(si+gbi[0])));
  float rv = gh*eh + gc*ec + gi*ei;
  sres[d] = rv;
  __syncthreads();
  for (int o=d; o<NOUT; o+=HD){
    float acc = bcls[o];
    for (int k=0; k<HD; k++) acc += sres[k]*Wc[(size_t)k*NOUT + o];
    out[(size_t)b*NOUT + o] = acc;
  }
}

// -------- InfoNCE loss (single block) --------------------------------------------------
__global__ void k_nce(float* __restrict__ out, int out_size){
  __shared__ float snorm[48];
  __shared__ float sE[256];
  int tid = threadIdx.x, wid = tid>>5, lane = tid&31;
  for (int row=wid; row<48; row+=8){
    const float* base = (row<16) ? (d_eh + row*HD)
                      : (row<32) ? (d_ec + (row-16)*HD)
                                 : (d_ei + (row-32)*HD);
    float s = 0.f;
    for (int d=lane; d<HD; d+=32){ float v = base[d]; s += v*v; }
    s = warp_sum(s);
    if (lane==0) snorm[row] = fmaxf(sqrtf(s), EPSF);
  }
  __syncthreads();
  float total = 0.f;
  for (int pair=0; pair<2; pair++){
    const float* Bm = pair ? d_ei : d_ec;
    int boff = pair ? 32 : 16;
    for (int idx=wid; idx<256; idx+=8){
      int i = idx>>4, j = idx&15;
      const float* a  = d_eh + i*HD;
      const float* bb = Bm   + j*HD;
      float s = 0.f;
      for (int d=lane; d<HD; d+=32) s += a[d]*bb[d];
      s = warp_sum(s);
      if (lane==0) sE[idx] = expf(s / (snorm[i]*snorm[boff+j]*0.4f));
    }
    __syncthreads();
    if (tid==0){
      float l = 0.f;
      for (int i=0;i<16;i++){
        float neg = 0.f;
        for (int j=0;j<16;j++) neg += sE[i*16+j];
        float pos = sE[i*16+i];
        l += -logf(pos/(neg + 1e-8f) + 1e-8f);
      }
      total += l/16.f;
    }
    __syncthreads();
  }
  if (tid==0 && out_size > NB*NOUT) out[NB*NOUT] = total;
}

// ==================================================================================
static cudaStream_t g_s1 = 0, g_s2 = 0, g_s3 = 0;
static cudaEvent_t  g_evR = 0, g_evB = 0, g_evC1 = 0, g_evC2 = 0;
static cudaEvent_t  g_evD = 0, g_evS1 = 0, g_evM1 = 0, g_evM2 = 0, g_evH = 0;

extern "C" void kernel_launch(void* const* d_in, const int* in_sizes, int n_in,
                              void* d_out, int out_size){
  (void)in_sizes; (void)n_in;
  const float* code_x = (const float*)d_in[0];
  const int*   lens   = (const int*)  d_in[1];
  const float* emb    = (const float*)d_in[2];
  const float* adj    = (const float*)d_in[3];
  const float* ln_g   = (const float*)d_in[4];
  const float* ln_b   = (const float*)d_in[5];
  const float* W_h    = (const float*)d_in[6];
  const float* b_h    = (const float*)d_in[7];
  const float* W_c    = (const float*)d_in[8];
  const float* b_c    = (const float*)d_in[9];
  const float* W_i    = (const float*)d_in[10];
  const float* b_i    = (const float*)d_in[11];
  const float* gw_h   = (const float*)d_in[12];
  const float* gb_h   = (const float*)d_in[13];
  const float* gw_c   = (const float*)d_in[14];
  const float* gb_c   = (const float*)d_in[15];
  const float* gw_i   = (const float*)d_in[16];
  const float* gb_i   = (const float*)d_in[17];
  const float* W_cls  = (const float*)d_in[18];
  const float* b_cls  = (const float*)d_in[19];
  float* out = (float*)d_out;

  if (!g_s1){
    cudaStreamCreateWithFlags(&g_s1, cudaStreamNonBlocking);
    cudaStreamCreateWithFlags(&g_s2, cudaStreamNonBlocking);
    cudaStreamCreateWithFlags(&g_s3, cudaStreamNonBlocking);
    cudaEventCreateWithFlags(&g_evR,  cudaEventDisableTiming);
    cudaEventCreateWithFlags(&g_evB,  cudaEventDisableTiming);
    cudaEventCreateWithFlags(&g_evC1, cudaEventDisableTiming);
    cudaEventCreateWithFlags(&g_evC2, cudaEventDisableTiming);
    cudaEventCreateWithFlags(&g_evD,  cudaEventDisableTiming);
    cudaEventCreateWithFlags(&g_evS1, cudaEventDisableTiming);
    cudaEventCreateWithFlags(&g_evM1, cudaEventDisableTiming);
    cudaEventCreateWithFlags(&g_evM2, cudaEventDisableTiming);
    cudaEventCreateWithFlags(&g_evH,  cudaEventDisableTiming);
  }

  // fork
  cudaEventRecord(g_evR, 0);
  cudaStreamWaitEvent(g_s1, g_evR, 0);
  cudaStreamWaitEvent(g_s2, g_evR, 0);
  cudaStreamWaitEvent(g_s3, g_evR, 0);

  // ---- branch B (s1): dual emb GEMM, then hidden tph ----
  k_gemm2<<<NC/16, 256, 0, g_s1>>>(emb, W_h, W_c);
  cudaEventRecord(g_evB, g_s1);

  // ---- branch C (s2 + s3): per-patient structure, then causal passes ----
  k_masks_compact<<<NB, 1024, 0, g_s2>>>(code_x, lens);
  cudaEventRecord(g_evC1, g_s2);
  k_degrees<<<dim3(NB, 16, 2), 256, 0, g_s2>>>();
  cudaEventRecord(g_evD, g_s2);

  // s1: tph (needs EWh + visit lists) -- fully hidden
  cudaStreamWaitEvent(g_s1, g_evC1, 0);
  k_tprime_h<<<dim3(NB, EV), 64, 0, g_s1>>>();
  cudaEventRecord(g_evH, g_s1);

  // s3: multi-bit pass1 (needs degrees + EWc only) -- overlaps kV1/kF1s
  cudaStreamWaitEvent(g_s3, g_evD, 0);
  cudaStreamWaitEvent(g_s3, g_evB, 0);
  kF1m<<<dim3(NB, (NC + RPB - 1)/RPB), 256, 0, g_s3>>>();
  cudaEventRecord(g_evM1, g_s3);

  // s2: V1 + single-bit pass1
  cudaStreamWaitEvent(g_s2, g_evB, 0);
  kV1 <<<dim3(NB, EV-1), 256, 0, g_s2>>>(lens);
  kF1s<<<dim3(NB, (NC + RPB - 1)/RPB), 256, 0, g_s2>>>();
  cudaEventRecord(g_evS1, g_s2);

  // s3: multi-bit pass2 (needs full yw) -- overlaps kW2/kF2s
  cudaStreamWaitEvent(g_s3, g_evS1, 0);
  kF2m<<<dim3(NB, (NC + RPB - 1)/RPB), 256, 0, g_s3>>>(b_c);
  cudaEventRecord(g_evM2, g_s3);

  // s2: W2 (needs full yw) + single-bit pass2
  cudaStreamWaitEvent(g_s2, g_evM1, 0);
  kW2 <<<dim3(NB, EV-1), 256, 0, g_s2>>>(lens);
  kF2s<<<dim3(NB, (NC + RPB - 1)/RPB), 256, 0, g_s2>>>(b_c);
  cudaStreamWaitEvent(g_s2, g_evM2, 0);
  cudaEventRecord(g_evC2, g_s2);

  // ---- branch A (stream 0): adj structure + icd chain ----
  k_zero<<<2, 1024>>>();
  k_csr_scat<<<(NC + 31)/32, 1024>>>(adj);
  k_spmm_rows<<<NC/4, 128>>>(emb, 0);
  k_spmm_cols_ln<<<NC/4, 128>>>(ln_g, ln_b);
  k_spmm_rows<<<NC/4, 128>>>(emb, 1);
  k_spmm_cols_ln<<<NC/4, 128>>>(ln_g, ln_b);
  k_spmm_rows<<<NC/4, 128>>>(emb, 1);
  k_spmm_cols_ln<<<NC/4, 128>>>(ln_g, ln_b);
  k_gemm1<<<NC/16, 256>>>(W_i);   // icd @ W_i

  // ---- join ----
  cudaStreamWaitEvent(0, g_evC1, 0);     // vl/vlen/Dvinv for tpi
  k_tprime_i<<<dim3(NB, EV), 64>>>();
  cudaStreamWaitEvent(0, g_evH, 0);      // tph ready
  cudaStreamWaitEvent(0, g_evC2, 0);     // zr from pass2
  k_poolpart<<<dim3(NB, PCH), 64>>>(b_h, b_i);
  k_finish_cls<<<NB, HD>>>(b_c, gw_h, gb_h, gw_c, gb_c, gw_i, gb_i, W_cls, b_cls, out);
  k_nce<<<1, 256>>>(out, out_size);
}